// round 17
// baseline (speedup 1.0000x reference)
#include <cuda_runtime.h>
#include <cuda_bf16.h>

#define KDIM 64
#define PF   4   // prefetch depth (steps)

__device__ float g_fwd[1024];
__device__ float g_gold[1024];
__device__ int   g_done = 0;

typedef unsigned long long ull;

__device__ __forceinline__ void fma2(ull& acc, ull a, ull b) {
    asm("fma.rn.f32x2 %0, %1, %2, %3;" : "=l"(acc) : "l"(a), "l"(b), "l"(acc));
}
__device__ __forceinline__ void add2(ull& d, ull a, ull b) {
    asm("add.rn.f32x2 %0, %1, %2;" : "=l"(d) : "l"(a), "l"(b));
}
__device__ __forceinline__ float sum2(ull v) {
    return __uint_as_float((unsigned)v) + __uint_as_float((unsigned)(v >> 32));
}

// ---------------- gold score: one 256-thread block per batch ----------------
__global__ __launch_bounds__(256)
void crf_gold_kernel(const float* __restrict__ emis,
                     const float* __restrict__ trans,
                     const float* __restrict__ start_t,
                     const float* __restrict__ end_t,
                     const int*  __restrict__ labels,
                     const int*  __restrict__ sent_len,
                     int T)
{
    const int b   = blockIdx.x;
    const int tid = threadIdx.x;
    const int L   = sent_len[b];
    const int*   lab = labels + (size_t)b * T;
    const float* em  = emis   + (size_t)b * T * KDIM;

    float s = 0.0f;
    for (int t = tid; t < L; t += 256) {
        const int lt = lab[t];
        float v = em[(size_t)t * KDIM + lt];
        v += (t == 0) ? start_t[lt] : trans[lab[t - 1] * KDIM + lt];
        s += v;
    }
    __shared__ float ws[8];
#pragma unroll
    for (int o = 16; o; o >>= 1) s += __shfl_xor_sync(0xffffffffu, s, o);
    if ((tid & 31) == 0) ws[tid >> 5] = s;
    __syncthreads();
    if (tid < 32) {
        float u = (tid < 8) ? ws[tid] : 0.0f;
#pragma unroll
        for (int o = 4; o; o >>= 1) u += __shfl_xor_sync(0xffffffffu, u, o);
        if (tid == 0) g_gold[b] = u + end_t[lab[L - 1]];
    }
}

// ------------- forward: 128-thread block = TWO independent batches -------------
// Warps {0,1} run batch 2*bid, warps {2,3} batch 2*bid+1; each half syncs with
// its own named barrier. Thread j owns column j; E = exp(trans) column in 32
// packed f32x2 regs. Linear-space recursion with exact power-of-2 renorm.
// R17: SPLIT-PHASE DOT — each warp first multiplies its OWN 32 alphas
// (readable after its own STS + fence, intra-warp, no barrier: R9-validated
// pattern), so the cross-warp barrier wait overlaps with real FMA work; the
// other half is consumed after the barrier.
__global__ __launch_bounds__(128, 1)
void crf_forward128(const float* __restrict__ emis,
                    const float* __restrict__ trans,
                    const float* __restrict__ start_t,
                    const float* __restrict__ end_t,
                    const int*  __restrict__ sent_len,
                    int T, int B, float* __restrict__ out)
{
    const int half = threadIdx.x >> 6;     // 0 or 1: which batch
    const int j    = threadIdx.x & 63;     // CRF column
    const int w    = j >> 5;               // warp within half (0 or 1)
    const int b    = 2 * blockIdx.x + half;
    const int L    = sent_len[b];
    const float* em = emis + (size_t)b * T * KDIM;
    const int barid = 1 + half;            // named barrier per half

    __shared__ __align__(16) float sa[2][2][KDIM];   // [half][buf][state]
    __shared__ float rsum[2][2];
    __shared__ int   sh_last;

    // E column j as 32 packed (i, i+1) f32x2 pairs -> 64 regs
    ull Epk[KDIM / 2];
#pragma unroll
    for (int i2 = 0; i2 < KDIM / 2; ++i2) {
        const float lo = __expf(trans[(2 * i2)     * KDIM + j]);
        const float hi = __expf(trans[(2 * i2 + 1) * KDIM + j]);
        Epk[i2] = (ull)__float_as_uint(lo) | ((ull)__float_as_uint(hi) << 32);
    }

    const int ob = 8 * w;                  // own-half ulonglong2 base
    const int xb = 8 - ob;                 // other-half base

    // t = 0
    float a = __expf(start_t[j] + em[j]);
    int   Stot = 0;

    // raw emission ring for steps t = 1..PF
    float er[PF];
#pragma unroll
    for (int k = 0; k < PF; ++k) {
        int tt = 1 + k; if (tt > T - 1) tt = T - 1;
        er[k] = em[(size_t)tt * KDIM + j];
    }

    int buf = 0;
    auto step = [&](float eraw) {
        const float P = __expf(eraw);      // consume-time exp (loaded PF ago)
        sa[half][buf][j] = a;
        asm volatile("" ::: "memory");     // order STS before own-half LDS
        const ulonglong2* sv = (const ulonglong2*)sa[half][buf];
        unsigned pb = 0;
        ull a0 = 0ull, a1 = 0ull, a2 = 0ull, a3 = 0ull;
        // phase 1: OWN half (intra-warp data, no barrier needed)
#pragma unroll
        for (int k = 0; k < 8; ++k) {
            const ulonglong2 v = sv[ob + k];
            if (k == 0 && w == 0) pb = (unsigned)v.x;   // pivot sa[0] (warp0)
            fma2(a0, v.x, Epk[2 * (ob + k)]);
            fma2(a1, v.y, Epk[2 * (ob + k) + 1]);
        }
        // barrier wait overlaps with phase-1 FMAs on both sides
        asm volatile("bar.sync %0, 64;" :: "r"(barid) : "memory");
        // phase 2: OTHER half
#pragma unroll
        for (int k = 0; k < 8; ++k) {
            const ulonglong2 v = sv[xb + k];
            if (k == 0 && w == 1) pb = (unsigned)v.x;   // pivot sa[0] (warp1)
            fma2(a2, v.x, Epk[2 * (xb + k)]);
            fma2(a3, v.y, Epk[2 * (xb + k) + 1]);
        }
        const int e = (int)((pb >> 23) & 0xffu);
        const float scl = __uint_as_float((unsigned)(254 - e) << 23); // 2^(127-e)
        const float sp  = scl * P;         // off the dependency chain
        Stot += e - 127;
        add2(a0, a0, a1);
        add2(a2, a2, a3);
        add2(a0, a0, a2);
        a = sum2(a0) * sp;
        buf ^= 1;
    };

    int t = 1;
    // fast path: refill indices t+PF .. t+2PF-1 all <= T-1, no clamping
    for (; t + PF <= L && t + 2 * PF - 1 <= T - 1; t += PF) {
        float nx[PF];
        const float* base = em + (size_t)(t + PF) * KDIM + j;
#pragma unroll
        for (int k = 0; k < PF; ++k)
            nx[k] = base[k * KDIM];        // 4 batched LDGs, MLP=4
#pragma unroll
        for (int k = 0; k < PF; ++k) {
            step(er[k]);
            er[k] = nx[k];
        }
    }
    // boundary path: clamped refill (at most ~2 groups)
    for (; t + PF <= L; t += PF) {
#pragma unroll
        for (int k = 0; k < PF; ++k) {
            const float ec = er[k];
            int tp = t + PF + k; if (tp > T - 1) tp = T - 1;
            er[k] = em[(size_t)tp * KDIM + j];
            step(ec);
        }
    }
    for (int k = 0; t < L; ++t, ++k)       // tail: ring already filled
        step(er[k]);

    // fwd = log( sum_j a[j]*exp(end[j]) ) + Stot*ln2   (per half)
    {
        float xs = a * __expf(end_t[j]);
#pragma unroll
        for (int o = 16; o; o >>= 1)
            xs += __shfl_xor_sync(0xffffffffu, xs, o);
        if ((j & 31) == 0) rsum[half][j >> 5] = xs;
        asm volatile("bar.sync %0, 64;" :: "r"(barid) : "memory");
        if (j == 0)
            g_fwd[b] = __logf(rsum[half][0] + rsum[half][1])
                     + (float)Stot * 0.69314718055994530942f;
    }

    // ---------------- finisher: last block reduces all partials ----------------
    __syncthreads();                       // both halves done, g_fwd written
    if (threadIdx.x == 0) {
        __threadfence();
        const int old = atomicAdd(&g_done, 1);
        sh_last = (old == gridDim.x - 1);
    }
    __syncthreads();
    if (sh_last) {
        __threadfence();
        float v = 0.0f;
        for (int i = threadIdx.x; i < B; i += 128) v += g_fwd[i] - g_gold[i];
#pragma unroll
        for (int o = 16; o; o >>= 1) v += __shfl_xor_sync(0xffffffffu, v, o);
        __shared__ float fin[4];
        if ((threadIdx.x & 31) == 0) fin[threadIdx.x >> 5] = v;
        __syncthreads();
        if (threadIdx.x == 0) {
            out[0] = (fin[0] + fin[1] + fin[2] + fin[3]) / (float)B;
            g_done = 0;                    // reset for next (deterministic) call
        }
    }
}

extern "C" void kernel_launch(void* const* d_in, const int* in_sizes, int n_in,
                              void* d_out, int out_size)
{
    const float* emis    = (const float*)d_in[0];
    const float* trans   = (const float*)d_in[1];
    const float* start_t = (const float*)d_in[2];
    const float* end_t   = (const float*)d_in[3];
    const int*   labels  = (const int*)d_in[4];
    const int*   slen    = (const int*)d_in[5];

    const int B = in_sizes[5];            // 512
    const int T = in_sizes[4] / B;        // 1024
    float* out = (float*)d_out;

    crf_gold_kernel<<<B, 256>>>(emis, trans, start_t, end_t, labels, slen, T);
    crf_forward128<<<B / 2, 128>>>(emis, trans, start_t, end_t, slen, T, B, out);
}